// round 5
// baseline (speedup 1.0000x reference)
#include <cuda_runtime.h>
#include <cuda_fp16.h>
#include <cstdint>

#define B_   128
#define T_   256
#define K_   256
#define NB   8
#define NTH  512
#define FS   260      // fstage row stride in floats (conflict-free)
#define ESS  264      // es row stride in halves   (conflict-free)
#define LOG2E 1.4426950408889634f
#define LN2   0.6931471805599453f

static __device__ __forceinline__ uint32_t packh2(float lo, float hi) {
    __half2 h = __floats2half2_rn(lo, hi);
    return *reinterpret_cast<uint32_t*>(&h);
}
static __device__ __forceinline__ void mma16816(float* d, const uint32_t* a,
                                                uint32_t b0, uint32_t b1) {
    asm volatile(
        "mma.sync.aligned.m16n8k16.row.col.f32.f16.f16.f32 "
        "{%0,%1,%2,%3}, {%4,%5,%6,%7}, {%8,%9}, {%0,%1,%2,%3};"
        : "+f"(d[0]), "+f"(d[1]), "+f"(d[2]), "+f"(d[3])
        : "r"(a[0]), "r"(a[1]), "r"(a[2]), "r"(a[3]), "r"(b0), "r"(b1));
}

__global__ __launch_bounds__(NTH, 1)
void crf_loss_kernel(const float* __restrict__ feats,   // [B,T,K]
                     const float* __restrict__ trans,   // [K,K]
                     const int*   __restrict__ tags,    // [B,T]
                     const int*   __restrict__ lens,    // [B]
                     float*       __restrict__ out)     // [B]
{
    __shared__ __align__(16) uint16_t es_s[2][NB * ESS];   // scaled exp(state), fp16
    __shared__ __align__(16) float    fst[2][NB * FS];     // staged emissions
    __shared__ __align__(16) float    stsh[NB * FS];       // final log states
    __shared__ int gsh[2][NB];

    const int tid  = threadIdx.x;
    const int lane = tid & 31;
    const int w    = tid >> 5;        // 16 warps, warp w -> rows [16w,16w+16)
    const int g    = lane >> 2;       // group id (A row offset / B col n)
    const int tg   = lane & 3;        // thread-in-group
    const int r0   = w * 16 + g;      // my rows: r0, r0+8
    const int c0   = 2 * tg;          // my batch cols: c0, c0+1
    const int c1   = c0 + 1;
    const int blk  = blockIdx.x;

    // staging role: thread stages 4 floats of batch sn at col sk
    const int sn = tid >> 6;
    const int sk = (tid & 63) * 4;
    const float* fsrc = feats + (size_t)(blk * NB + sn) * T_ * K_ + sk;

    // ---- lens ----
    int len0 = 1, len1 = 1, maxlen = 1;
    #pragma unroll
    for (int j = 0; j < NB; ++j) {
        int l = __ldg(lens + blk * NB + j);
        if (j == c0) len0 = l;
        if (j == c1) len1 = l;
        maxlen = max(maxlen, l);
    }

    // ---- A fragments in registers: A[r][k] = exp(trans[k][r]) as fp16 ----
    uint32_t A[16][4];
    #pragma unroll
    for (int kt = 0; kt < 16; ++kt) {
        const int k0 = kt * 16 + tg * 2;
        float e00 = __expf(__ldg(trans + (size_t)k0 * K_ + r0));
        float e01 = __expf(__ldg(trans + (size_t)(k0 + 1) * K_ + r0));
        float e10 = __expf(__ldg(trans + (size_t)k0 * K_ + r0 + 8));
        float e11 = __expf(__ldg(trans + (size_t)(k0 + 1) * K_ + r0 + 8));
        float e02 = __expf(__ldg(trans + (size_t)(k0 + 8) * K_ + r0));
        float e03 = __expf(__ldg(trans + (size_t)(k0 + 9) * K_ + r0));
        float e12 = __expf(__ldg(trans + (size_t)(k0 + 8) * K_ + r0 + 8));
        float e13 = __expf(__ldg(trans + (size_t)(k0 + 9) * K_ + r0 + 8));
        A[kt][0] = packh2(e00, e01);
        A[kt][1] = packh2(e10, e11);
        A[kt][2] = packh2(e02, e03);
        A[kt][3] = packh2(e12, e13);
    }

    // ---- init: stage f0, compute g0, v0, es[0], stage f1 ----
    *reinterpret_cast<float4*>(&fst[0][sn * FS + sk]) =
        *reinterpret_cast<const float4*>(fsrc);            // f_0
    __syncthreads();
    if (tid < 4) {                                          // w==0, g==0 -> r0==0
        gsh[0][c0] = __float2int_rd(fst[0][c0 * FS] * LOG2E) + 14;
        gsh[0][c1] = __float2int_rd(fst[0][c1 * FS] * LOG2E) + 14;
    }
    int tn0 = (maxlen > 1) ? 1 : 0;
    float4 fw0 = *reinterpret_cast<const float4*>(fsrc + (size_t)tn0 * K_);
    __syncthreads();
    *reinterpret_cast<float4*>(&fst[1][sn * FS + sk]) = fw0;  // f_1

    int   G0 = gsh[0][c0], G1 = gsh[0][c1];
    int   C0 = G0, C1 = G1;
    float v0 = exp2f(fst[0][c0 * FS + r0]     * LOG2E - (float)G0);
    float v1 = exp2f(fst[0][c1 * FS + r0]     * LOG2E - (float)G1);
    float v2 = exp2f(fst[0][c0 * FS + r0 + 8] * LOG2E - (float)G0);
    float v3 = exp2f(fst[0][c1 * FS + r0 + 8] * LOG2E - (float)G1);
    es_s[0][c0 * ESS + r0]     = __half_as_ushort(__float2half_rn(v0));
    es_s[0][c1 * ESS + r0]     = __half_as_ushort(__float2half_rn(v1));
    es_s[0][c0 * ESS + r0 + 8] = __half_as_ushort(__float2half_rn(v2));
    es_s[0][c1 * ESS + r0 + 8] = __half_as_ushort(__float2half_rn(v3));
    __syncthreads();

    // ---- forward recurrence ----
    for (int t = 1; t < maxlen; ++t) {
        const int p = (t - 1) & 1;     // read buffers
        const int q = t & 1;           // fst[q] holds f_t; write es[q], gsh[q]

        const int tn = (t + 1 < maxlen) ? (t + 1) : t;
        float4 fw = *reinterpret_cast<const float4*>(fsrc + (size_t)tn * K_);

        const int gp0 = gsh[p][c0], gp1 = gsh[p][c1];
        float ef0 = exp2f(fst[q][c0 * FS + r0]     * LOG2E - (float)gp0);
        float ef1 = exp2f(fst[q][c1 * FS + r0]     * LOG2E - (float)gp1);
        float ef2 = exp2f(fst[q][c0 * FS + r0 + 8] * LOG2E - (float)gp0);
        float ef3 = exp2f(fst[q][c1 * FS + r0 + 8] * LOG2E - (float)gp1);

        // matvec: D[256,8] = A * ES, 2-way k-split accumulators
        float da[4] = {0.f, 0.f, 0.f, 0.f};
        float db[4] = {0.f, 0.f, 0.f, 0.f};
        const uint16_t* esp = &es_s[p][g * ESS];   // B col n = g
        #pragma unroll
        for (int kt = 0; kt < 16; ++kt) {
            uint32_t b0 = *reinterpret_cast<const uint32_t*>(esp + kt * 16 + tg * 2);
            uint32_t b1 = *reinterpret_cast<const uint32_t*>(esp + kt * 16 + tg * 2 + 8);
            mma16816((kt < 8) ? da : db, A[kt], b0, b1);
        }

        *reinterpret_cast<float4*>(&fst[p][sn * FS + sk]) = fw;  // stage f_{t+1}

        float d0 = da[0] + db[0], d1 = da[1] + db[1];
        float d2 = da[2] + db[2], d3 = da[3] + db[3];
        if (t < len0) { v0 = d0 * ef0; v2 = d2 * ef2; C0 += gp0; }
        if (t < len1) { v1 = d1 * ef1; v3 = d3 * ef3; C1 += gp1; }

        if (tid < 4) {                 // r0 == 0 owners publish next normalizer
            gsh[q][c0] = ((__float_as_int(v0) >> 23) & 255) - 113;
            gsh[q][c1] = ((__float_as_int(v1) >> 23) & 255) - 113;
        }
        es_s[q][c0 * ESS + r0]     = __half_as_ushort(__float2half_rn(v0));
        es_s[q][c1 * ESS + r0]     = __half_as_ushort(__float2half_rn(v1));
        es_s[q][c0 * ESS + r0 + 8] = __half_as_ushort(__float2half_rn(v2));
        es_s[q][c1 * ESS + r0 + 8] = __half_as_ushort(__float2half_rn(v3));
        __syncthreads();
    }

    // ---- final log-domain states ----
    stsh[c0 * FS + r0]     = (log2f(v0) + (float)C0) * LN2;
    stsh[c1 * FS + r0]     = (log2f(v1) + (float)C1) * LN2;
    stsh[c0 * FS + r0 + 8] = (log2f(v2) + (float)C0) * LN2;
    stsh[c1 * FS + r0 + 8] = (log2f(v3) + (float)C1) * LN2;
    __syncthreads();

    // ---- per-batch epilogue: warp w < 8 handles batch j = w ----
    if (w < NB) {
        const int j  = w;
        const int bg = blk * NB + j;
        const int lb = __ldg(lens + bg);

        float sv[8];
        #pragma unroll
        for (int i = 0; i < 8; ++i) sv[i] = stsh[j * FS + lane + 32 * i];

        float bm = sv[0];
        #pragma unroll
        for (int i = 1; i < 8; ++i) bm = fmaxf(bm, sv[i]);
        #pragma unroll
        for (int o = 16; o > 0; o >>= 1)
            bm = fmaxf(bm, __shfl_xor_sync(0xffffffffu, bm, o));

        float ss = 0.f;
        #pragma unroll
        for (int i = 0; i < 8; ++i) ss += __expf(sv[i] - bm);
        #pragma unroll
        for (int o = 16; o > 0; o >>= 1)
            ss += __shfl_xor_sync(0xffffffffu, ss, o);
        float forward = bm + __logf(ss);

        float u = 0.f;
        #pragma unroll
        for (int i = 0; i < 8; ++i) {
            int tp = lane + 32 * i;
            if (tp < lb) {
                int tgd = tags[bg * T_ + tp];
                u += feats[(size_t)bg * T_ * K_ + (size_t)tp * K_ + tgd];
                if (tp + 1 < lb) {
                    int tg2 = tags[bg * T_ + tp + 1];
                    u += __ldg(trans + (size_t)tgd * K_ + tg2);
                }
            }
        }
        #pragma unroll
        for (int o = 16; o > 0; o >>= 1)
            u += __shfl_xor_sync(0xffffffffu, u, o);
        if (lane == 0) out[bg] = forward - u;
    }
}

extern "C" void kernel_launch(void* const* d_in, const int* in_sizes, int n_in,
                              void* d_out, int out_size) {
    const float* feats = (const float*)d_in[0];
    const float* trans = (const float*)d_in[1];
    const int*   tags  = (const int*)d_in[2];
    const int*   lens  = (const int*)d_in[3];
    float*       out   = (float*)d_out;

    crf_loss_kernel<<<B_ / NB, NTH>>>(feats, trans, tags, lens, out);
}